// round 17
// baseline (speedup 1.0000x reference)
#include <cuda_runtime.h>
#include <cuda_bf16.h>
#include <cstdint>

// ---------------------------------------------------------------------------
// Problem constants
// ---------------------------------------------------------------------------
#define NB 128          // batch
#define NA 64           // agents
#define NM 512          // map tokens
#define NH 128          // hidden
#define NHEAD 8
#define HD 16           // head dim
#define NROWS (NB*NA)   // 8192
#define KVROWS (NB*NM)  // 65536

// ---------------------------------------------------------------------------
// Scratch (device globals — allocation-free)
// ---------------------------------------------------------------------------
__device__ float g_kh[KVROWS*NH];      // 32 MB precomputed K heads
__device__ float g_vh[KVROWS*NH];      // 32 MB precomputed V heads
__device__ float g_state[NROWS*2];
__device__ float g_hA[NROWS*NH];       // h ping
__device__ float g_hB[NROWS*NH];       // h pong
__device__ float g_c[NROWS*NH];
__device__ float g_q[NROWS*NH];        // Q (from fused MLP)
__device__ float g_attn[NROWS*NH];     // attention output
__device__ float g_maskadd[NB*NM];     // additive attention mask (0 / -1e30)
__device__ int   g_curav[NROWS];       // current availability (0/1)
__device__ int   g_viol[4];            // dtype-detector flags (monotone)
__device__ float g_biasg[512];         // bias quads: biasg[u*4 + gate]
__device__ float g_Wq3[128*64];        // wq @ enc_w3
__device__ float g_bq3[128];           // wq @ enc_b3 + bq
// split-bf16 MMA operands (plain row-major, K=256)
__device__ unsigned short g_Whi[512*256];   // folded gate weights, permuted cols
__device__ unsigned short g_Wlo[512*256];
__device__ unsigned short g_Xhi[NROWS*256]; // [attn|h] per step
__device__ unsigned short g_Xlo[NROWS*256];

// ---------------------------------------------------------------------------
// Packed fp32x2 FMA (Blackwell FFMA2) + helpers
// ---------------------------------------------------------------------------
__device__ __forceinline__ float2 ffma2(float2 a, float2 b, float2 c) {
    unsigned long long ua = *reinterpret_cast<unsigned long long*>(&a);
    unsigned long long ub = *reinterpret_cast<unsigned long long*>(&b);
    unsigned long long uc = *reinterpret_cast<unsigned long long*>(&c);
    unsigned long long ud;
    asm("fma.rn.f32x2 %0, %1, %2, %3;" : "=l"(ud) : "l"(ua), "l"(ub), "l"(uc));
    return *reinterpret_cast<float2*>(&ud);
}
__device__ __forceinline__ float2 shfl_xor_f2(float2 v, int m) {
    unsigned long long u = *reinterpret_cast<unsigned long long*>(&v);
    u = __shfl_xor_sync(0xffffffffu, u, m);
    return *reinterpret_cast<float2*>(&u);
}
__device__ __forceinline__ float2 add2(float2 a, float2 b) {
    return make_float2(a.x + b.x, a.y + b.y);
}
__device__ __forceinline__ float sigm(float x) {
    return 1.0f / (1.0f + __expf(-x));
}
__device__ __forceinline__ unsigned short f2bf(float x) {
    unsigned short u;
    asm("cvt.rn.bf16.f32 %0, %1;" : "=h"(u) : "f"(x));
    return u;
}
__device__ __forceinline__ float bf2f(unsigned short u) {
    float f;
    asm("cvt.f32.bf16 %0, %1;" : "=f"(f) : "h"(u));
    return f;
}
// baseline sm_80+ tensor op — assembles for plain sm_103
__device__ __forceinline__ void mma_bf16(float* d, uint32_t a0, uint32_t a1,
                                         uint32_t a2, uint32_t a3,
                                         uint32_t b0, uint32_t b1) {
    asm volatile("mma.sync.aligned.m16n8k16.row.col.f32.bf16.bf16.f32 "
                 "{%0,%1,%2,%3}, {%4,%5,%6,%7}, {%8,%9}, {%0,%1,%2,%3};"
                 : "+f"(d[0]), "+f"(d[1]), "+f"(d[2]), "+f"(d[3])
                 : "r"(a0), "r"(a1), "r"(a2), "r"(a3), "r"(b0), "r"(b1));
}

// W column permutation: unit u's 4 gates land in ONE thread's C fragment.
// P(u, gate): within a 64-col tile (colTile = u>>4):
//   wn = (u>>3)&1, ul = u&7, q = ul&3, hs = ul>>2,
//   na = ((gate>>1)<<1) + hs, e = gate&1, P = wn*32 + na*8 + q*2 + e.
__device__ __forceinline__ int wcol_perm(int u, int gate) {
    int colTile = u >> 4;
    int wn = (u >> 3) & 1;
    int ul = u & 7;
    int q  = ul & 3;
    int hs = ul >> 2;
    int na = ((gate >> 1) << 1) + hs;
    int e  = gate & 1;
    return colTile*64 + wn*32 + na*8 + q*2 + e;
}

// ---------------------------------------------------------------------------
// Launch 1: bool-dtype detector for both masks (monotone flags).
// ---------------------------------------------------------------------------
__global__ void detect_both(const unsigned int* __restrict__ pm,
                            const unsigned int* __restrict__ pc)
{
    int i = blockIdx.x*blockDim.x + threadIdx.x;
    if (i < NB*NM/4) {
        unsigned int w = pm[i];
        if (w > 1u)                      atomicOr(&g_viol[0], 1);
        if (w != 0u && w != 0x3F800000u) atomicOr(&g_viol[1], 1);
    } else if (i < NB*NM/4 + NROWS/4) {
        unsigned int w = pc[i - NB*NM/4];
        if (w > 1u)                      atomicOr(&g_viol[2], 1);
        if (w != 0u && w != 0x3F800000u) atomicOr(&g_viol[3], 1);
    }
}

__device__ __forceinline__ bool read_bool(const void* p, int idx, int viol32, int violf32)
{
    if (viol32 == 0)  return ((const int*)p)[idx] != 0;
    if (violf32 == 0) return ((const float*)p)[idx] != 0.0f;
    return ((const unsigned char*)p)[idx] != 0;
}

// ---------------------------------------------------------------------------
// Launch 2: MERGED setup. Blocks [0,1024): KV head projections (FFMA2 GEMM).
// Blocks [1024,1536): init + masks + weight folding + split-bf16 W bake.
// ---------------------------------------------------------------------------
#define XS_LD 132
__global__ __launch_bounds__(256)
void setup_kernel(const float* __restrict__ feat,
                  const float* __restrict__ hidden,
                  const float* __restrict__ context,
                  const void*  __restrict__ map_avail,
                  const void*  __restrict__ cur_avail,
                  const float* __restrict__ map_emb,
                  const float* __restrict__ wk, const float* __restrict__ bk,
                  const float* __restrict__ wv, const float* __restrict__ bv,
                  const float* __restrict__ w_ih, const float* __restrict__ w_hh,
                  const float* __restrict__ wo,   const float* __restrict__ b_ih,
                  const float* __restrict__ b_hh, const float* __restrict__ bo,
                  const float* __restrict__ wq,   const float* __restrict__ enc_w3,
                  const float* __restrict__ bq,   const float* __restrict__ enc_b3)
{
    if (blockIdx.x < 1024) {
        const int z  = blockIdx.x >> 9;          // 0 = K, 1 = V
        const int bx = blockIdx.x & 511;
        const float* W    = (z == 0) ? wk : wv;
        const float* bias = (z == 0) ? bk : bv;
        float*       Y    = (z == 0) ? g_kh : g_vh;

        __shared__ float Xs[32][XS_LD];
        __shared__ float Ws[32][XS_LD];

        const int tid = threadIdx.x;
        const int tx = tid & 15;
        const int ty = tid >> 4;
        const int rowBase = bx << 7;
        const int cx = tx << 2;

        float2 acc[8][4];
        #pragma unroll
        for (int i = 0; i < 8; ++i)
            #pragma unroll
            for (int jj = 0; jj < 4; ++jj)
                acc[i][jj] = make_float2(0.0f, 0.0f);

        for (int k0 = 0; k0 < NH; k0 += 32) {
            #pragma unroll
            for (int i = 0; i < 4; ++i) {
                int s = tid + (i << 8);
                int r = s >> 3, kq = (s & 7) << 2;
                float4 v = *reinterpret_cast<const float4*>(&map_emb[(size_t)(rowBase + r)*NH + k0 + kq]);
                Xs[kq + 0][r] = v.x; Xs[kq + 1][r] = v.y;
                Xs[kq + 2][r] = v.z; Xs[kq + 3][r] = v.w;
            }
            #pragma unroll
            for (int i = 0; i < 4; ++i) {
                int s = tid + (i << 8);
                int j = s >> 3, kq = (s & 7) << 2;
                float4 v = *reinterpret_cast<const float4*>(&W[(size_t)j*NH + k0 + kq]);
                Ws[kq + 0][j] = v.x; Ws[kq + 1][j] = v.y;
                Ws[kq + 2][j] = v.z; Ws[kq + 3][j] = v.w;
            }
            __syncthreads();

            #pragma unroll 8
            for (int k = 0; k < 32; ++k) {
                float4 a0 = *reinterpret_cast<const float4*>(&Xs[k][ty << 3]);
                float4 a1 = *reinterpret_cast<const float4*>(&Xs[k][(ty << 3) + 4]);
                float4 b0 = *reinterpret_cast<const float4*>(&Ws[k][cx]);
                float4 b1 = *reinterpret_cast<const float4*>(&Ws[k][cx + 64]);
                float2 b0l = make_float2(b0.x, b0.y), b0h = make_float2(b0.z, b0.w);
                float2 b1l = make_float2(b1.x, b1.y), b1h = make_float2(b1.z, b1.w);
                float ar[8] = {a0.x, a0.y, a0.z, a0.w, a1.x, a1.y, a1.z, a1.w};
                #pragma unroll
                for (int i = 0; i < 8; ++i) {
                    float2 av = make_float2(ar[i], ar[i]);
                    acc[i][0] = ffma2(av, b0l, acc[i][0]);
                    acc[i][1] = ffma2(av, b0h, acc[i][1]);
                    acc[i][2] = ffma2(av, b1l, acc[i][2]);
                    acc[i][3] = ffma2(av, b1h, acc[i][3]);
                }
            }
            __syncthreads();
        }

        float4 bi0 = *reinterpret_cast<const float4*>(&bias[cx]);
        float4 bi1 = *reinterpret_cast<const float4*>(&bias[cx + 64]);
        #pragma unroll
        for (int i = 0; i < 8; ++i) {
            int r = rowBase + (ty << 3) + i;
            float4 v0 = make_float4(acc[i][0].x + bi0.x, acc[i][0].y + bi0.y,
                                    acc[i][1].x + bi0.z, acc[i][1].y + bi0.w);
            float4 v1 = make_float4(acc[i][2].x + bi1.x, acc[i][2].y + bi1.y,
                                    acc[i][3].x + bi1.z, acc[i][3].y + bi1.w);
            *reinterpret_cast<float4*>(&Y[(size_t)r*NH + cx])      = v0;
            *reinterpret_cast<float4*>(&Y[(size_t)r*NH + cx + 64]) = v1;
        }
    } else {
        const int bid = blockIdx.x - 1024;           // 0..511
        const int idx = bid*256 + threadIdx.x;       // 0..131071

        for (int i = idx; i < NROWS*NH; i += 512*256) {
            g_hA[i] = hidden[i];
            g_c[i]  = context[i];
        }
        if (idx < NROWS*2) g_state[idx] = feat[idx];

        // gate fold -> split-bf16 W at permuted column positions
        {
            int j = idx >> 8, k = idx & 255;      // j = gate*128 + u (original row)
            int gate = j >> 7, u = j & 127;
            float v;
            if (k < 128) {
                float acc = 0.0f;
                #pragma unroll 4
                for (int d = 0; d < 128; ++d) acc += w_ih[j*128 + d] * wo[d*128 + k];
                v = acc;
            } else {
                v = w_hh[j*128 + (k - 128)];
            }
            unsigned short hi = f2bf(v);
            unsigned short lo = f2bf(v - bf2f(hi));
            int dst = wcol_perm(u, gate);
            g_Whi[(size_t)dst*256 + k] = hi;
            g_Wlo[(size_t)dst*256 + k] = lo;
        }
        if (idx < 512) {
            // biasg[u*4 + gate]
            int u = idx >> 2, gate = idx & 3;
            int jb = gate*128 + u;
            float acc = b_ih[jb] + b_hh[jb];
            #pragma unroll 4
            for (int d = 0; d < 128; ++d) acc += w_ih[jb*128 + d] * bo[d];
            g_biasg[idx] = acc;
        }
        if (idx < 128*64) {
            int j = idx >> 6, k = idx & 63;
            float acc = 0.0f;
            #pragma unroll 4
            for (int d = 0; d < 128; ++d) acc += wq[j*128 + d] * enc_w3[d*64 + k];
            g_Wq3[j*64 + k] = acc;
            if (idx < 128) {
                float a = bq[idx];
                #pragma unroll 4
                for (int d = 0; d < 128; ++d) a += wq[idx*128 + d] * enc_b3[d];
                g_bq3[idx] = a;
            }
        }
        int v32m = g_viol[0], vf32m = g_viol[1];
        int v32c = g_viol[2], vf32c = g_viol[3];
        if (idx < NB*NM)
            g_maskadd[idx] = read_bool(map_avail, idx, v32m, vf32m) ? 0.0f : -1e30f;
        if (idx < NROWS)
            g_curav[idx] = read_bool(cur_avail, idx, v32c, vf32c) ? 1 : 0;
    }
}

// ---------------------------------------------------------------------------
// xconv: per step, X = [attn|h] fp32 -> row-major split-bf16. grid 1024, 256.
// ---------------------------------------------------------------------------
__global__ __launch_bounds__(256)
void xconv_kernel(const float* __restrict__ attn, const float* __restrict__ hin)
{
    int gid = blockIdx.x*256 + threadIdx.x;   // 0 .. 262143
    int row = gid >> 5;
    int k0  = (gid & 31) << 3;                // 8 consecutive k
    const float* src = (k0 < 128) ? &attn[(size_t)row*NH + k0]
                                  : &hin[(size_t)row*NH + (k0 - 128)];
    float4 v0 = *reinterpret_cast<const float4*>(src);
    float4 v1 = *reinterpret_cast<const float4*>(src + 4);
    float x[8] = {v0.x, v0.y, v0.z, v0.w, v1.x, v1.y, v1.z, v1.w};
    unsigned short hi[8], lo[8];
    #pragma unroll
    for (int i = 0; i < 8; ++i) {
        hi[i] = f2bf(x[i]);
        lo[i] = f2bf(x[i] - bf2f(hi[i]));
    }
    uint4 ph, pl;
    ph.x = (uint32_t)hi[0] | ((uint32_t)hi[1] << 16);
    ph.y = (uint32_t)hi[2] | ((uint32_t)hi[3] << 16);
    ph.z = (uint32_t)hi[4] | ((uint32_t)hi[5] << 16);
    ph.w = (uint32_t)hi[6] | ((uint32_t)hi[7] << 16);
    pl.x = (uint32_t)lo[0] | ((uint32_t)lo[1] << 16);
    pl.y = (uint32_t)lo[2] | ((uint32_t)lo[3] << 16);
    pl.z = (uint32_t)lo[4] | ((uint32_t)lo[5] << 16);
    pl.w = (uint32_t)lo[6] | ((uint32_t)lo[7] << 16);
    *reinterpret_cast<uint4*>(&g_Xhi[(size_t)row*256 + k0]) = ph;
    *reinterpret_cast<uint4*>(&g_Xlo[(size_t)row*256 + k0]) = pl;
}

// ---------------------------------------------------------------------------
// Gates GEMM v4: HMMA split-bf16 (mma.sync m16n8k16) + fused LSTM epilogue.
// grid (64 rowTiles, 8 colTiles), 256 threads = 8 warps (4 M x 2 N).
// D[128,64] = Xhi*Whi^T + Xhi*Wlo^T + Xlo*Whi^T, fp32 accum in registers.
// K=256 streamed in 4 chunks of 64 through padded smem (stride 72, conflict-free).
// ---------------------------------------------------------------------------
#define GP 72                             // padded k-stride (bf16 elems)
#define OFF_AHI 0
#define OFF_ALO (128*GP)
#define OFF_WHI (2*128*GP)
#define OFF_WLO (2*128*GP + 64*GP)
#define GATES_SMEM ((2*128*GP + 2*64*GP)*2)   // 55,296 bytes

__global__ __launch_bounds__(256)
void gates_lstm(const float* __restrict__ hin, float* __restrict__ hout)
{
    extern __shared__ __align__(16) unsigned short smg[];
    unsigned short* Ahi = smg + OFF_AHI;
    unsigned short* Alo = smg + OFF_ALO;
    unsigned short* Whi = smg + OFF_WHI;
    unsigned short* Wlo = smg + OFF_WLO;

    const int tid  = threadIdx.x;
    const int wid  = tid >> 5;
    const int lane = tid & 31;
    const int wm   = wid & 3;            // M quadrant (32 rows)
    const int wn   = wid >> 2;           // N half (32 cols)
    const int rowTile = blockIdx.x;
    const int colTile = blockIdx.y;
    const int ar = lane >> 2;            // fragment row 0..7
    const int aq = lane & 3;             // fragment col quad

    float acc[2][4][4];                  // [ma][na][reg]
    #pragma unroll
    for (int ma = 0; ma < 2; ++ma)
        #pragma unroll
        for (int na = 0; na < 4; ++na)
            #pragma unroll
            for (int r = 0; r < 4; ++r) acc[ma][na][r] = 0.0f;

    for (int kc = 0; kc < 4; ++kc) {
        const int kbase = kc << 6;
        // stage A (128 x 64 bf16, hi+lo): 8 uint4 per row
        for (int i = tid; i < 1024; i += 256) {
            int r = i >> 3, c = i & 7;
            *reinterpret_cast<uint4*>(&Ahi[r*GP + c*8]) =
                *reinterpret_cast<const uint4*>(&g_Xhi[(size_t)(rowTile*128 + r)*256 + kbase + c*8]);
            *reinterpret_cast<uint4*>(&Alo[r*GP + c*8]) =
                *reinterpret_cast<const uint4*>(&g_Xlo[(size_t)(rowTile*128 + r)*256 + kbase + c*8]);
        }
        // stage W (64 x 64 bf16, hi+lo)
        for (int i = tid; i < 512; i += 256) {
            int r = i >> 3, c = i & 7;
            *reinterpret_cast<uint4*>(&Whi[r*GP + c*8]) =
                *reinterpret_cast<const uint4*>(&g_Whi[(size_t)(colTile*64 + r)*256 + kbase + c*8]);
            *reinterpret_cast<uint4*>(&Wlo[r*GP + c*8]) =
                *reinterpret_cast<const uint4*>(&g_Wlo[(size_t)(colTile*64 + r)*256 + kbase + c*8]);
        }
        __syncthreads();

        #pragma unroll
        for (int ks = 0; ks < 4; ++ks) {
            const int kk = ks << 4;
            // A fragments (hi, lo) for 2 M atoms
            uint32_t fahi[2][4], falo[2][4];
            #pragma unroll
            for (int ma = 0; ma < 2; ++ma) {
                int r0 = wm*32 + ma*16 + ar;
                int base0 = r0*GP + kk + aq*2;
                int base1 = (r0 + 8)*GP + kk + aq*2;
                fahi[ma][0] = *reinterpret_cast<const uint32_t*>(&Ahi[base0]);
                fahi[ma][1] = *reinterpret_cast<const uint32_t*>(&Ahi[base1]);
                fahi[ma][2] = *reinterpret_cast<const uint32_t*>(&Ahi[base0 + 8]);
                fahi[ma][3] = *reinterpret_cast<const uint32_t*>(&Ahi[base1 + 8]);
                falo[ma][0] = *reinterpret_cast<const uint32_t*>(&Alo[base0]);
                falo[ma][1] = *reinterpret_cast<const uint32_t*>(&Alo[base1]);
                falo[ma][2] = *reinterpret_cast<const uint32_t*>(&Alo[base0 + 8]);
                falo[ma][3] = *reinterpret_cast<const uint32_t*>(&Alo[base1 + 8]);
            }
            // B fragments (hi, lo) for 4 N atoms
            uint32_t fbhi[4][2], fblo[4][2];
            #pragma unroll
            for (int na = 0; na < 4; ++na) {
                int cn = wn*32 + na*8 + ar;
                int base = cn*GP + kk + aq*2;
                fbhi[na][0] = *reinterpret_cast<const uint32_t*>(&Whi[base]);
                fbhi[na][1] = *reinterpret_cast<const uint32_t*>(&Whi[base + 8]);
                fblo[na][0] = *reinterpret_cast<const uint32_t*>(&Wlo[base]);
                fblo[na][1] = *reinterpret_cast<const uint32_t*>(&Wlo[base + 8]);
            }
            // combos outermost: same-acc MMAs are 8 apart (latency hidden)
            #pragma unroll
            for (int ma = 0; ma < 2; ++ma)
                #pragma unroll
                for (int na = 0; na < 4; ++na)
                    mma_bf16(acc[ma][na], fahi[ma][0], fahi[ma][1], fahi[ma][2], fahi[ma][3],
                             fbhi[na][0], fbhi[na][1]);
            #pragma unroll
            for (int ma = 0; ma < 2; ++ma)
                #pragma unroll
                for (int na = 0; na < 4; ++na)
                    mma_bf16(acc[ma][na], fahi[ma][0], fahi[ma][1], fahi[ma][2], fahi[ma][3],
                             fblo[na][0], fblo[na][1]);
            #pragma unroll
            for (int ma = 0; ma < 2; ++ma)
                #pragma unroll
                for (int na = 0; na < 4; ++na)
                    mma_bf16(acc[ma][na], falo[ma][0], falo[ma][1], falo[ma][2], falo[ma][3],
                             fbhi[na][0], fbhi[na][1]);
        }
        __syncthreads();
    }

    // LSTM epilogue. Thread's C fragment: atom (ma,na), regs:
    //   d0=(r0, c), d1=(r0, c+1), d2=(r0+8, c), d3=(r0+8, c+1),  c = na*8 + aq*2.
    // Permutation puts unit u = colTile*16 + wn*8 + (q + 4*hs) gates at
    // na = 2*(gate>>1) + hs, e = gate&1 -> for hs=0: unit q, gates from na 0,2;
    // hs=1: unit q+4, gates from na 1,3.
    #pragma unroll
    for (int ma = 0; ma < 2; ++ma) {
        #pragma unroll
        for (int rr = 0; rr < 2; ++rr) {     // r0 and r0+8
            int row = rowTile*128 + wm*32 + ma*16 + ar + rr*8;
            int av = g_curav[row];
            #pragma unroll
            for (int hs = 0; hs < 2; ++hs) {
                int u = colTile*16 + wn*8 + aq + hs*4;
                float gi = acc[ma][0 + hs][rr*2 + 0];
                float gf = acc[ma][0 + hs][rr*2 + 1];
                float gg = acc[ma][2 + hs][rr*2 + 0];
                float go = acc[ma][2 + hs][rr*2 + 1];
                float4 bb = *reinterpret_cast<const float4*>(&g_biasg[u*4]);
                gi += bb.x; gf += bb.y; gg += bb.z; go += bb.w;
                if (av) {
                    float co = g_c[(size_t)row*NH + u];
                    float cn = sigm(gf)*co + sigm(gi)*tanhf(gg);
                    float hn = sigm(go)*tanhf(cn);
                    g_c[(size_t)row*NH + u] = cn;
                    hout[(size_t)row*NH + u] = hn;
                } else {
                    hout[(size_t)row*NH + u] = hin[(size_t)row*NH + u];
                }
            }
        }
    }
}

// ---------------------------------------------------------------------------
// Fused [state update + out write] + MLP + Q projection (16 rows/block).
// ---------------------------------------------------------------------------
__global__ __launch_bounds__(256)
void mlpq_kernel(const float* __restrict__ W1, const float* __restrict__ B1,
                 const float* __restrict__ W2, const float* __restrict__ B2,
                 const float* __restrict__ h_in,
                 const float* __restrict__ lin_w, const float* __restrict__ lin_b,
                 float* __restrict__ out, int t, int T)
{
    __shared__ float s0[16][2];
    __shared__ float h1[16][128];
    __shared__ float h2[16][68];

    const int tid = threadIdx.x;
    const int rb = blockIdx.x << 4;

    if (t > 0) {
        const int w = tid >> 5, lane = tid & 31;
        float4 w0 = *reinterpret_cast<const float4*>(&lin_w[lane*4]);
        float4 w1v = *reinterpret_cast<const float4*>(&lin_w[128 + lane*4]);
        #pragma unroll
        for (int j = 0; j < 2; ++j) {
            int row = rb + w*2 + j;
            float4 hv = *reinterpret_cast<const float4*>(&h_in[(size_t)row*NH + lane*4]);
            float2 d;
            d.x = hv.x*w0.x + hv.y*w0.y + hv.z*w0.z + hv.w*w0.w;
            d.y = hv.x*w1v.x + hv.y*w1v.y + hv.z*w1v.z + hv.w*w1v.w;
            #pragma unroll
            for (int off = 16; off > 0; off >>= 1)
                d = add2(d, shfl_xor_f2(d, off));
            if (lane == 0) {
                float a = g_state[row*2 + 0] + d.x + lin_b[0];
                float b = g_state[row*2 + 1] + d.y + lin_b[1];
                g_state[row*2 + 0] = a;
                g_state[row*2 + 1] = b;
                out[((size_t)row*T + (t - 1))*2 + 0] = a;
                out[((size_t)row*T + (t - 1))*2 + 1] = b;
                s0[row - rb][0] = a;
                s0[row - rb][1] = b;
            }
        }
    } else {
        for (int s = tid; s < 32; s += 256)
            s0[s >> 1][s & 1] = g_state[rb*2 + s];
    }
    __syncthreads();

    for (int idx = tid; idx < 2048; idx += 256) {
        int r = idx >> 7, j = idx & 127;
        float v = s0[r][0]*W1[2*j] + s0[r][1]*W1[2*j + 1] + B1[j];
        h1[r][j] = fmaxf(v, 0.0f);
    }
    __syncthreads();

    for (int idx = tid; idx < 1024; idx += 256) {
        int r = idx >> 6, j = idx & 63;
        float acc = B2[j];
        const float4* wr = reinterpret_cast<const float4*>(&W2[j*128]);
        const float4* hr = reinterpret_cast<const float4*>(&h1[r][0]);
        #pragma unroll 8
        for (int kq = 0; kq < 32; ++kq) {
            float4 wv = __ldg(&wr[kq]);
            float4 hv = hr[kq];
            acc += wv.x*hv.x + wv.y*hv.y + wv.z*hv.z + wv.w*hv.w;
        }
        h2[r][j] = fmaxf(acc, 0.0f);
    }
    __syncthreads();

    for (int idx = tid; idx < 2048; idx += 256) {
        int r = idx >> 7, j = idx & 127;
        float acc = g_bq3[j];
        const float4* wr = reinterpret_cast<const float4*>(&g_Wq3[j*64]);
        const float4* hr = reinterpret_cast<const float4*>(&h2[r][0]);
        #pragma unroll
        for (int kq = 0; kq < 16; ++kq) {
            float4 wv = __ldg(&wr[kq]);
            float4 hv = hr[kq];
            acc += wv.x*hv.x + wv.y*hv.y + wv.z*hv.z + wv.w*hv.w;
        }
        g_q[(size_t)(rb + r)*NH + j] = acc;
    }
}

// ---------------------------------------------------------------------------
// Cross-attention v6 (unchanged): broadcast LDS.128, raw-exp softmax.
// ---------------------------------------------------------------------------
#define A5_SMEM ((2*NM*16 + NM)*4)   // 67,584 bytes

__global__ __launch_bounds__(256, 2)
void attn_kernel()
{
    extern __shared__ float sm[];
    float4* ks4   = reinterpret_cast<float4*>(sm);
    float4* vs4   = reinterpret_cast<float4*>(sm + NM*16);
    float*  maskS = sm + 2*NM*16;
    float*  mgbuf = sm;   // reused for merge after the main loop

    const int tid  = threadIdx.x;
    const int b    = blockIdx.x >> 3;
    const int head = blockIdx.x & 7;
    const size_t kvbase = (size_t)b*NM*NH + head*HD;

    for (int idx = tid; idx < NM*4; idx += 256) {
        int m = idx >> 2, c = idx & 3;
        ks4[idx] = *reinterpret_cast<const float4*>(&g_kh[kvbase + (size_t)m*NH + (c << 2)]);
        vs4[idx] = *reinterpret_cast<const float4*>(&g_vh[kvbase + (size_t)m*NH + (c << 2)]);
    }
    for (int m = tid; m < NM; m += 256)
        maskS[m] = g_maskadd[b*NM + m];
    __syncthreads();

    const int w = tid >> 5, lane = tid & 31;
    const int ms = w << 6;
    const int rA = b*NA + lane;
    const int rB = rA + 32;

    float2 qA[8], qB[8];
    #pragma unroll
    for (int dq = 0; dq < 8; ++dq) {
        float2 va = *reinterpret_cast<const float2*>(&g_q[(size_t)rA*NH + head*HD + 2*dq]);
        float2 vb = *reinterpret_cast<const float2*>(&g_q[(size_t)rB*NH + head*HD + 2*dq]);
        qA[dq] = make_float2(va.x*0.25f, va.y*0.25f);
        qB[dq] = make_float2(vb.x*0.25f, vb.y*0.25f);
    }

    float sumA = 0.0f, sumB = 0.0f;
    float2 oA[8], oB[8];
    #pragma unroll
    for (int dq = 0; dq < 8; ++dq) {
        oA[dq] = make_float2(0.0f, 0.0f);
        oB[dq] = make_float2(0.0f, 0.0f);
    }

    #pragma unroll 2
    for (int mi = 0; mi < 64; mi += 2) {
        int m = ms + mi;
        const float4* kr = &ks4[m << 2];
        float4 k0 = kr[0], k1 = kr[1], k2 = kr[2], k3 = kr[3];
        float4 k4 = kr[4], k5 = kr[5], k6 = kr[6], k7 = kr[7];
        float2 kk0[8] = {{k0.x,k0.y},{k0.z,k0.w},{k1.x,k1.y},{k1.z,k1.w},
                         {k2.x,k2.y},{k2.z,k2.w},{k3.x,k3.y},{k3.z,k3.w}};
        float2 kk1[8] = {{k4.x,k4.y},{k4.z,k4.w},{k5.x,k5.y},{k5.z,k5.w},
                         {k6.x,k6.y},{k6.z,k6.w},{k7.x,k7.y},{k7.z,k7.w}};

        float2 aA1 = make_float2(0.0f, 0.0f), aA2 = make_float2(0.0f, 0.0f);
        float2 aB1 = make_float2(0.0f, 0.0f), aB2 = make_float2(0.0f, 0.0f);
        #pragma unroll
        for (int dq = 0; dq < 8; ++dq) {
            aA1 = ffma2(qA[dq], kk0[dq], aA1);
            aA2 = ffma2(qA[dq], kk1[dq], aA2);
            aB1 = ffma2(qB[dq], kk0[dq], aB1);
            aB2 = ffma2(qB[dq], kk1[dq], aB2);
        }
        float m0 = maskS[m], m1 = maskS[m + 1];
        float pA1 = __expf(aA1.x + aA1.y + m0);
        float pA2 = __expf(aA2.x + aA2.y + m1);
        float pB1 = __expf(aB1.x + aB1.y + m0);
        float pB2 = __expf(aB2.x + aB2.y + m1);
        sumA += pA1 + pA2;
        sumB += pB1 + pB2;

        const float4* vr = &vs4[m << 2];
        float4 v0 = vr[0], v1 = vr[1], v2 = vr[2], v3 = vr[3];
        float4 v4 = vr[4], v5 = vr[5], v6 = vr[6], v7 = vr[7];
        float2 vv0[8] = {{v0.x,v0.y},{v0.z,v0.w},{v1.x,v1.y},{v1.z,v1.w},
                         {v2.x,v2.y},{v2.z,v2.w},{v3.x,v3.y},{v3.z,v3.w}};
        float2 vv1[8] = {{v4.x,v4.y},{v4.z,v4.w},{v5.x,v5.y},{v5.z,v5.w},
                         {v6.x,v6.y},{v6.z,v6.w},{v7.x,v7.y},{v7.z,v7.w}};

        float2 pA12 = make_float2(pA1, pA1);
        float2 pA22 = make_float2(pA2, pA2);
        float2 pB12 = make_float2(pB1, pB1);
        float2 pB22 = make_float2(pB2, pB2);
        #pragma unroll
        for (int dq = 0; dq < 8; ++dq) {
            oA[dq] = ffma2(pA12, vv0[dq], oA[dq]);
            oA[dq] = ffma2(pA22, vv1[dq], oA[dq]);
            oB[dq] = ffma2(pB12, vv0[dq], oB[dq]);
            oB[dq] = ffma2(pB22, vv1[dq], oB[dq]);
        }
    }

    __syncthreads();
    {
        float* mgA = &mgbuf[(size_t)(w*64 + lane)*20];
        mgA[0] = sumA;
        #pragma unroll
        for (int dq = 0; dq < 8; ++dq)
            *reinterpret_cast<float2*>(&mgA[2 + 2*dq]) = oA[dq];
        float* mgB = &mgbuf[(size_t)(w*64 + 32 + lane)*20];
        mgB[0] = sumB;
        #pragma unroll
        for (int dq = 0; dq < 8; ++dq)
            *reinterpret_cast<float2*>(&mgB[2 + 2*dq]) = oB[dq];
    }
    __syncthreads();

    if (w < 2) {
        const int qid = (w << 5) + lane;
        float S = 0.0f;
        float2 oo[8];
        #pragma unroll
        for (int dq = 0; dq < 8; ++dq) oo[dq] = make_float2(0.0f, 0.0f);
        #pragma unroll
        for (int p = 0; p < 8; ++p) {
            const float* mg = &mgbuf[(size_t)(p*64 + qid)*20];
            S += mg[0];
            #pragma unroll
            for (int dq = 0; dq < 8; ++dq) {
                float2 ov = *reinterpret_cast<const float2*>(&mg[2 + 2*dq]);
                oo[dq] = add2(oo[dq], ov);
            }
        }
        float inv = 1.0f / S;
        int rq = b*NA + qid;
        float* dst = &g_attn[(size_t)rq*NH + head*HD];
        #pragma unroll
        for (int dq = 0; dq < 8; ++dq) {
            float2 v = oo[dq];
            *reinterpret_cast<float2*>(&dst[2*dq]) = make_float2(v.x*inv, v.y*inv);
        }
    }
}

// ---------------------------------------------------------------------------
// Final output slice
// ---------------------------------------------------------------------------
__global__ __launch_bounds__(256)
void final_out(const float* __restrict__ h_in,
               const float* __restrict__ lin_w, const float* __restrict__ lin_b,
               float* __restrict__ out, int T)
{
    const int w = threadIdx.x >> 5, lane = threadIdx.x & 31;
    const int row = blockIdx.x*8 + w;
    float4 hv = *reinterpret_cast<const float4*>(&h_in[(size_t)row*NH + lane*4]);
    float4 w0 = *reinterpret_cast<const float4*>(&lin_w[lane*4]);
    float4 w1 = *reinterpret_cast<const float4*>(&lin_w[128 + lane*4]);
    float2 d;
    d.x = hv.x*w0.x + hv.y*w0.y + hv.z*w0.z + hv.w*w0.w;
    d.y = hv.x*w1.x + hv.y*w1.y + hv.z*w1.z + hv.w*w1.w;
    #pragma unroll
    for (int off = 16; off > 0; off >>= 1)
        d = add2(d, shfl_xor_f2(d, off));
    if (lane == 0) {
        float a = g_state[row*2 + 0] + d.x + lin_b[0];
        float b = g_state[row*2 + 1] + d.y + lin_b[1];
        out[((size_t)row*T + (T - 1))*2 + 0] = a;
        out[((size_t)row*T + (T - 1))*2 + 1] = b;
    }
}

// ---------------------------------------------------------------------------
// Host orchestration (graph-capturable; attn stays at launch slot 4)
// ---------------------------------------------------------------------------
extern "C" void kernel_launch(void* const* d_in, const int* in_sizes, int n_in,
                              void* d_out, int out_size)
{
    const float* feat      = (const float*)d_in[0];
    const void*  cur_avail = d_in[1];
    const float* hidden    = (const float*)d_in[2];
    const float* context   = (const float*)d_in[3];
    const float* map_emb   = (const float*)d_in[4];
    const void*  map_avail = d_in[5];

    const int wb = n_in - 20;  // weights are the LAST 20 inputs
    const float* enc_w1 = (const float*)d_in[wb + 0];
    const float* enc_b1 = (const float*)d_in[wb + 1];
    const float* enc_w2 = (const float*)d_in[wb + 2];
    const float* enc_b2 = (const float*)d_in[wb + 3];
    const float* enc_w3 = (const float*)d_in[wb + 4];
    const float* enc_b3 = (const float*)d_in[wb + 5];
    const float* wq     = (const float*)d_in[wb + 6];
    const float* bq     = (const float*)d_in[wb + 7];
    const float* wk     = (const float*)d_in[wb + 8];
    const float* bk     = (const float*)d_in[wb + 9];
    const float* wv     = (const float*)d_in[wb + 10];
    const float* bv     = (const float*)d_in[wb + 11];
    const float* wo     = (const float*)d_in[wb + 12];
    const float* bo     = (const float*)d_in[wb + 13];
    const float* w_ih   = (const float*)d_in[wb + 14];
    const float* w_hh   = (const float*)d_in[wb + 15];
    const float* b_ih   = (const float*)d_in[wb + 16];
    const float* b_hh   = (const float*)d_in[wb + 17];
    const float* lin_w  = (const float*)d_in[wb + 18];
    const float* lin_b  = (const float*)d_in[wb + 19];

    float* out = (float*)d_out;
    const int T = out_size / (NROWS*2);

    float *p_attn, *p_hA, *p_hB;
    cudaGetSymbolAddress((void**)&p_attn, g_attn);
    cudaGetSymbolAddress((void**)&p_hA,   g_hA);
    cudaGetSymbolAddress((void**)&p_hB,   g_hB);

    cudaFuncSetAttribute(attn_kernel,
                         cudaFuncAttributeMaxDynamicSharedMemorySize, A5_SMEM);
    cudaFuncSetAttribute(gates_lstm,
                         cudaFuncAttributeMaxDynamicSharedMemorySize, GATES_SMEM);

    detect_both<<<(NB*NM/4 + NROWS/4 + 255)/256, 256>>>(
        (const unsigned int*)map_avail, (const unsigned int*)cur_avail);
    setup_kernel<<<1536, 256>>>(feat, hidden, context, map_avail, cur_avail,
                                map_emb, wk, bk, wv, bv,
                                w_ih, w_hh, wo, b_ih, b_hh, bo,
                                wq, enc_w3, bq, enc_b3);

    for (int t = 0; t < T; ++t) {
        const float* h_in  = ((t & 1) == 0) ? p_hA : p_hB;
        float*       h_out = ((t & 1) == 0) ? p_hB : p_hA;
        mlpq_kernel<<<NROWS/16, 256>>>(enc_w1, enc_b1, enc_w2, enc_b2,
                                       h_in, lin_w, lin_b, out, t, T);
        attn_kernel<<<NB*NHEAD, 256, A5_SMEM>>>();
        xconv_kernel<<<1024, 256>>>(p_attn, h_in);
        gates_lstm<<<dim3(64, 8), 256, GATES_SMEM>>>(h_in, h_out);
    }
    const float* h_fin = ((T & 1) == 0) ? p_hA : p_hB;
    final_out<<<NROWS/8, 256>>>(h_fin, lin_w, lin_b, out, T);
}